// round 16
// baseline (speedup 1.0000x reference)
#include <cuda_runtime.h>
#include <cuda_fp16.h>
#include <math.h>
#include <stdint.h>

#define B_   2
#define T_   2048
#define C_   1024
#define H_   16
#define HD_  64
#define WIN_ 512
#define M_   (B_ * T_)

// ---------------------------------------------------------------------------
// Device scratch (allocation-free) — single fp16 everywhere
// ---------------------------------------------------------------------------
__device__ __half g_q16[(size_t)B_ * H_ * T_ * HD_];
__device__ __half g_k16[(size_t)B_ * H_ * T_ * HD_];
__device__ __half g_v16[(size_t)B_ * H_ * T_ * HD_];
__device__ __half g_x16[(size_t)M_ * C_];
__device__ __half g_w16[(size_t)4 * C_ * C_];   // Wq,Wk,Wv,Wo stacked
__device__ __half g_att16[(size_t)M_ * C_];

// ---------------------------------------------------------------------------
// PTX helpers — compute_80-compatible only
// ---------------------------------------------------------------------------
__device__ __forceinline__ uint32_t smem_u32(const void* p) {
    uint32_t a;
    asm("{ .reg .u64 t; cvta.to.shared.u64 t, %1; cvt.u32.u64 %0, t; }"
        : "=r"(a) : "l"(p));
    return a;
}

__device__ __forceinline__ void cp16(uint32_t s, const void* g) {
    asm volatile("cp.async.cg.shared.global [%0], [%1], 16;" :: "r"(s), "l"(g));
}
__device__ __forceinline__ void cp_commit() { asm volatile("cp.async.commit_group;"); }
__device__ __forceinline__ void cp_wait1()  { asm volatile("cp.async.wait_group 1;" ::: "memory"); }
__device__ __forceinline__ void cp_wait2()  { asm volatile("cp.async.wait_group 2;" ::: "memory"); }

__device__ __forceinline__ void ldmx4(uint32_t& r0, uint32_t& r1, uint32_t& r2, uint32_t& r3,
                                      uint32_t addr) {
    asm volatile("ldmatrix.sync.aligned.m8n8.x4.shared.b16 {%0,%1,%2,%3}, [%4];"
                 : "=r"(r0), "=r"(r1), "=r"(r2), "=r"(r3) : "r"(addr));
}
__device__ __forceinline__ void ldmx4t(uint32_t& r0, uint32_t& r1, uint32_t& r2, uint32_t& r3,
                                       uint32_t addr) {
    asm volatile("ldmatrix.sync.aligned.m8n8.x4.trans.shared.b16 {%0,%1,%2,%3}, [%4];"
                 : "=r"(r0), "=r"(r1), "=r"(r2), "=r"(r3) : "r"(addr));
}

// fp16 MMA, fp32 accumulate. Not volatile — ptxas may schedule.
__device__ __forceinline__ void mma16816(float* c, const uint32_t* a, const uint32_t* b) {
    asm("mma.sync.aligned.m16n8k16.row.col.f32.f16.f16.f32 "
        "{%0,%1,%2,%3}, {%4,%5,%6,%7}, {%8,%9}, {%0,%1,%2,%3};"
        : "+f"(c[0]), "+f"(c[1]), "+f"(c[2]), "+f"(c[3])
        : "r"(a[0]), "r"(a[1]), "r"(a[2]), "r"(a[3]), "r"(b[0]), "r"(b[1]));
}

// pack two fp32 into fp16x2 (a -> low half, b -> high half)
__device__ __forceinline__ uint32_t pk16(float a, float b) {
    uint32_t r;
    asm("cvt.rn.f16x2.f32 %0, %1, %2;" : "=r"(r) : "f"(b), "f"(a));
    return r;
}
// 2^x elementwise on fp16x2
__device__ __forceinline__ uint32_t h2exp2(uint32_t x) {
    uint32_t r;
    asm("ex2.approx.f16x2 %0, %1;" : "=r"(r) : "r"(x));
    return r;
}

// ---------------------------------------------------------------------------
// fp32 -> fp16 conversion (x and the 4 weight matrices).
// Grid-stride, 4 float4 per thread (2048 blocks x 256 thr x 4 = 2097152).
// ---------------------------------------------------------------------------
__global__ __launch_bounds__(256)
void conv_kernel(const float* __restrict__ x,
                 const float* __restrict__ wq, const float* __restrict__ wk,
                 const float* __restrict__ wv, const float* __restrict__ wo)
{
    int i = blockIdx.x * 256 + threadIdx.x;
#pragma unroll
    for (int it = 0; it < 4; it++, i += 2048 * 256) {
        const float* src;
        __half* dst;
        size_t off;
        if (i < 1048576) {
            src = x + (size_t)i * 4;
            dst = g_x16; off = (size_t)i * 4;
        } else {
            const int r = i - 1048576;
            const int w = r >> 18;
            const float* ws = (w == 0) ? wq : (w == 1) ? wk : (w == 2) ? wv : wo;
            src = ws + (size_t)(r & 262143) * 4;
            dst = g_w16; off = (size_t)r * 4;
        }
        const float4 v = *(const float4*)src;
        *(uint32_t*)(dst + off)     = pk16(v.x, v.y);
        *(uint32_t*)(dst + off + 2) = pk16(v.z, v.w);
    }
}

// ---------------------------------------------------------------------------
// fp16 mma.sync GEMM (unchanged from round 15).
// CTA 128x128, BK=64, 128 threads: 4 warps as 2(M) x 2(N), warp tile 64x64.
// 2 CTAs/SM. 3-stage cp.async, one barrier/chunk.
// MODE 0: out -> fp16 q/k/v in [B,H,T,hd]; Q scaled by log2(e)/8.
// MODE 1: A = g_att16, W = Wo; out = fp32 [M,C].
// ---------------------------------------------------------------------------
#define STG_BYTES 32768              // A 16KB @0, B 16KB @16384
#define GEMM_SMEM (3 * STG_BYTES)    // 98304

template <int MODE>
__global__ void __launch_bounds__(128, 2)
gemm_mma(float* __restrict__ out)
{
    extern __shared__ char smem_raw[];
    const uint32_t smem = smem_u32(smem_raw);

    const int tid  = threadIdx.x;
    const int wid  = tid >> 5;
    const int lane = tid & 31;
    const int col0 = blockIdx.x * 128;
    const int row0 = blockIdx.y * 128;
    const int z    = blockIdx.z;

    const int wrow = wid & 1;        // M: 2 warps x 64
    const int wcol = wid >> 1;       // N: 2 warps x 64

    const __half* A16 = (MODE == 0) ? g_x16 : g_att16;
    const size_t woff = (MODE == 0 ? (size_t)z : 3) * ((size_t)C_ * C_);

    const __half* a16 = A16 + (size_t)row0 * C_;
    const __half* b16 = g_w16 + woff + (size_t)col0 * C_;

    auto load_stage = [&](int chunk, int s) {
        const int k0 = chunk * 64;
        const uint32_t st = smem + (uint32_t)s * STG_BYTES;
#pragma unroll
        for (int q = 0; q < 8; q++) {               // 1024 slots each for A,B
            const int slot = tid + q * 128;
            const int rr = slot >> 3;               // row 0..127
            const int ch = slot & 7;
            const uint32_t so = (uint32_t)(rr * 128 + ((ch ^ (rr & 7)) << 4));
            const size_t   go = (size_t)rr * C_ + k0 + ch * 8;
            cp16(st +         so, a16 + go);
            cp16(st + 16384 + so, b16 + go);
        }
        cp_commit();
    };

    float c[4][8][4];
#pragma unroll
    for (int mf = 0; mf < 4; mf++)
#pragma unroll
        for (int nf = 0; nf < 8; nf++)
#pragma unroll
            for (int e = 0; e < 4; e++) c[mf][nf][e] = 0.f;

    // ldmatrix lane pieces (row offset + swizzle key, bytes)
    const int      rA    = lane & 15;
    const uint32_t aRow  = (uint32_t)(rA * 128);
    const uint32_t aSw   = (uint32_t)((rA & 7) << 4);
    const uint32_t aCb   = (uint32_t)((lane >> 4) << 4);          // 0 or 16
    const int      rB    = (lane & 7) + ((lane & 16) >> 1);
    const uint32_t bRow  = (uint32_t)(rB * 128);
    const uint32_t bSw   = (uint32_t)((rB & 7) << 4);
    const uint32_t bCb   = (uint32_t)((lane & 8) << 1);           // 0 or 16

    load_stage(0, 0);
    load_stage(1, 1);

    for (int ck = 0; ck < 16; ck++) {
        cp_wait1();
        __syncthreads();
        if (ck + 2 < 16) load_stage(ck + 2, (ck + 2) % 3);
        else             cp_commit();                  // keep group count uniform

        const uint32_t st = smem + (uint32_t)(ck % 3) * STG_BYTES;
        const uint32_t Abase = st + (uint32_t)(wrow * 8192) + aRow;           // 64 rows
        const uint32_t Bbase = st + 16384 + (uint32_t)(wcol * 8192) + bRow;   // 64 rows

#pragma unroll
        for (int k16 = 0; k16 < 4; k16++) {
            const uint32_t ca = ((aCb + (uint32_t)(k16 * 32)) ^ aSw);
            const uint32_t cb = ((bCb + (uint32_t)(k16 * 32)) ^ bSw);
            uint32_t af[4][4];
#pragma unroll
            for (int mf = 0; mf < 4; mf++) {
                const uint32_t a = Abase + (uint32_t)(mf * 2048) + ca;
                ldmx4(af[mf][0], af[mf][1], af[mf][2], af[mf][3], a);
            }
#pragma unroll
            for (int np = 0; np < 4; np++) {
                const uint32_t b = Bbase + (uint32_t)(np * 2048) + cb;
                uint32_t b0[2], b1[2];
                ldmx4(b0[0], b0[1], b1[0], b1[1], b);
                const int nf = np * 2;
#pragma unroll
                for (int mf = 0; mf < 4; mf++) mma16816(c[mf][nf],     af[mf], b0);
#pragma unroll
                for (int mf = 0; mf < 4; mf++) mma16816(c[mf][nf + 1], af[mf], b1);
            }
        }
    }

    // ---- epilogue ----
    const int group = lane >> 2;
    const int tq    = lane & 3;
#pragma unroll
    for (int mf = 0; mf < 4; mf++) {
#pragma unroll
        for (int nf = 0; nf < 8; nf++) {
            const int ncol = wcol * 64 + nf * 8 + tq * 2;
#pragma unroll
            for (int half = 0; half < 2; half++) {
                const int mrow = wrow * 64 + mf * 16 + group + half * 8;
                const int m = row0 + mrow;
                if (MODE == 0) {
                    __half* dst;
                    float sc;
                    // Q scale folds softmax 1/sqrt(64) AND log2(e).
                    if (z == 0)      { dst = g_q16; sc = 0.18033688011f; }
                    else if (z == 1) { dst = g_k16; sc = 1.0f;   }
                    else             { dst = g_v16; sc = 1.0f;   }
                    const uint32_t hv = pk16(c[mf][nf][half * 2]     * sc,
                                             c[mf][nf][half * 2 + 1] * sc);
                    const int n = col0 + ncol;
                    const int b = m >> 11;
                    const int t = m & (T_ - 1);
                    const int h = n >> 6;
                    const int d = n & 63;
                    const size_t idx = (((size_t)(b * H_ + h) * T_) + t) * HD_ + d;
                    *(uint32_t*)&dst[idx] = hv;
                } else {
                    const float2 v2 = make_float2(c[mf][nf][half * 2],
                                                  c[mf][nf][half * 2 + 1]);
                    *(float2*)&out[(size_t)m * C_ + col0 + ncol] = v2;
                }
            }
        }
    }
}

// ---------------------------------------------------------------------------
// fp16 tensor-core sliding-window flash attention — base-2 softmax,
// ones-MMA row sums (round 15), plus long-tiles-first CTA ordering:
// q-blocks 4..11 have 18 KV tiles, edges as few as 10; launching long blocks
// first puts the short ones in the trailing wave, shrinking the tail.
// CTA: 128 q x one (b,h); 128 threads: 4 warps x 32 q rows. 2 CTAs/SM.
// ---------------------------------------------------------------------------
#define ATT_STAGE  16384                          // K @0 (8KB), V @8192 (8KB)
#define ATT_SMEM   (3 * ATT_STAGE + 16384)        // 65536
#define MASKV      (-3.3e38f)

__global__ void __launch_bounds__(128, 2)
attn_mma()
{
    extern __shared__ char sraw[];
    const uint32_t ST = smem_u32(sraw);
    const uint32_t Qb = ST + 3 * ATT_STAGE;       // 16 KB Q region

    const int bh  = blockIdx.y;
    // long-first q-block permutation: {4..11, 3,12, 2,13, 1,14, 0,15}
    int qx;
    {
        const int bx = blockIdx.x;
        if (bx < 8) qx = 4 + bx;
        else {
            const int r = bx - 8;
            qx = (r & 1) ? (12 + (r >> 1)) : (3 - (r >> 1));
        }
    }
    const int q0  = qx * 128;
    const int tid = threadIdx.x;
    const int w    = tid >> 5;
    const int lane = tid & 31;

    // ---- Q staging ----
    {
        const __half* q16 = g_q16 + ((size_t)bh * T_ + q0) * HD_;
#pragma unroll
        for (int t = 0; t < 8; t++) {
            const int slot = tid + t * 128;        // 0..1023
            const int row = slot >> 3, ch = slot & 7;
            const uint32_t so = (uint32_t)(row * 128 + ((ch ^ (row & 7)) << 4));
            cp16(Qb + so, q16 + (size_t)row * HD_ + ch * 8);
        }
        cp_commit();
    }

    int kstart = q0 - (WIN_ - 1);
    if (kstart < 0) kstart = 0;
    kstart &= ~63;
    int kend = q0 + 128 + (WIN_ - 1);
    if (kend > T_) kend = T_;
    const int ntiles = (kend - kstart + 63) >> 6;

    auto load_stage = [&](int i) {
        const int kb = kstart + i * 64;
        if (kb < kend) {
            const uint32_t Sb = ST + (uint32_t)(i % 3) * ATT_STAGE;
            const size_t gb = ((size_t)bh * T_ + kb) * HD_;
#pragma unroll
            for (int t = 0; t < 4; t++) {
                const int slot = tid + t * 128;    // 0..511
                const int row = slot >> 3, ch = slot & 7;
                const uint32_t so = (uint32_t)(row * 128 + ((ch ^ (row & 7)) << 4));
                const size_t   go = gb + (size_t)row * HD_ + ch * 8;
                cp16(Sb +        so, g_k16 + go);
                cp16(Sb + 8192 + so, g_v16 + go);
            }
        }
        cp_commit();
    };

    load_stage(0);
    load_stage(1);
    cp_wait2();              // Q ready (stages 0,1 may still be in flight)
    __syncthreads();

    // ---- Q fragments to registers: 2 mf x 4 ks ----
    uint32_t qf[2][4][4];
    {
        const uint32_t qSw  = (uint32_t)((lane & 7) << 4);
        const uint32_t qCb  = (uint32_t)((lane >> 4) << 4);
#pragma unroll
        for (int mf = 0; mf < 2; mf++) {
            const uint32_t qRow = (uint32_t)((w * 32 + mf * 16 + (lane & 15)) * 128);
#pragma unroll
            for (int ks = 0; ks < 4; ks++) {
                const uint32_t a = Qb + qRow + ((qCb + (uint32_t)(ks * 32)) ^ qSw);
                ldmx4(qf[mf][ks][0], qf[mf][ks][1], qf[mf][ks][2], qf[mf][ks][3], a);
            }
        }
    }

    float m[2][2];
#pragma unroll
    for (int mf = 0; mf < 2; mf++) { m[mf][0] = MASKV; m[mf][1] = MASKV; }
    float lacc[2][4];                 // row-sum accumulator fragments (ones-MMA)
#pragma unroll
    for (int mf = 0; mf < 2; mf++)
#pragma unroll
        for (int e = 0; e < 4; e++) lacc[mf][e] = 0.f;
    float o[2][8][4];
#pragma unroll
    for (int mf = 0; mf < 2; mf++)
#pragma unroll
        for (int nf = 0; nf < 8; nf++)
#pragma unroll
            for (int e = 0; e < 4; e++) o[mf][nf][e] = 0.f;

    const uint32_t onesb[2] = {0x3C003C00u, 0x3C003C00u};   // fp16 1.0 x4

    const int g  = lane >> 2;
    const int tq = lane & 3;
    const int qr0 = q0 + w * 32 + g;

    const int      rK   = (lane & 7) + ((lane & 16) >> 1);
    const uint32_t kRow = (uint32_t)(rK * 128);
    const uint32_t kSw  = (uint32_t)((rK & 7) << 4);
    const uint32_t kCb  = (uint32_t)((lane & 8) << 1);            // 0 or 16
    const int      rV   = lane & 15;
    const uint32_t vRow = (uint32_t)(rV * 128);
    const uint32_t vSw  = (uint32_t)((rV & 7) << 4);
    const uint32_t vCb  = (uint32_t)(lane & 16);                  // 0 or 16

    for (int i = 0; i < ntiles; i++) {
        cp_wait1();
        __syncthreads();
        load_stage(i + 2);   // overwrites stage consumed at i-1

        const uint32_t Sb = ST + (uint32_t)(i % 3) * ATT_STAGE;
        const int kb = kstart + i * 64;

        // ---- S = Q K^T (log2-domain scores) ----
        float c[2][8][4];
#pragma unroll
        for (int mf = 0; mf < 2; mf++)
#pragma unroll
            for (int nf = 0; nf < 8; nf++)
#pragma unroll
                for (int e = 0; e < 4; e++) c[mf][nf][e] = 0.f;

#pragma unroll
        for (int ks = 0; ks < 4; ks++) {
            const uint32_t cc = (kCb + (uint32_t)(ks * 32)) ^ kSw;
#pragma unroll
            for (int np = 0; np < 4; np++) {
                const uint32_t addr = Sb + (uint32_t)(np * 2048) + kRow + cc;
                uint32_t b0[2], b1[2];
                ldmx4(b0[0], b0[1], b1[0], b1[1], addr);
                mma16816(c[0][2*np],     qf[0][ks], b0);
                mma16816(c[1][2*np],     qf[1][ks], b0);
                mma16816(c[0][2*np + 1], qf[0][ks], b1);
                mma16816(c[1][2*np + 1], qf[1][ks], b1);
            }
        }

        // ---- mask (edge tiles only) ----
        if (kb < q0 - 384 || kb > q0 + 448) {
#pragma unroll
            for (int mf = 0; mf < 2; mf++)
#pragma unroll
                for (int nf = 0; nf < 8; nf++)
#pragma unroll
                    for (int e = 0; e < 4; e++) {
                        const int key = kb + nf * 8 + tq * 2 + (e & 1);
                        const int qq  = qr0 + mf * 16 + ((e >> 1) << 3);
                        const int d   = qq - key;
                        if (d > (WIN_ - 1) || d < -(WIN_ - 1)) c[mf][nf][e] = MASKV;
                    }
        }

        // ---- online softmax (base 2): max, correct, subtract ----
#pragma unroll
        for (int mf = 0; mf < 2; mf++) {
            float rm0 = MASKV, rm1 = MASKV;
#pragma unroll
            for (int nf = 0; nf < 8; nf++) {
                rm0 = fmaxf(rm0, fmaxf(c[mf][nf][0], c[mf][nf][1]));
                rm1 = fmaxf(rm1, fmaxf(c[mf][nf][2], c[mf][nf][3]));
            }
            rm0 = fmaxf(rm0, __shfl_xor_sync(0xffffffff, rm0, 1));
            rm0 = fmaxf(rm0, __shfl_xor_sync(0xffffffff, rm0, 2));
            rm1 = fmaxf(rm1, __shfl_xor_sync(0xffffffff, rm1, 1));
            rm1 = fmaxf(rm1, __shfl_xor_sync(0xffffffff, rm1, 2));

            const float mn0 = fmaxf(m[mf][0], rm0);
            const float mn1 = fmaxf(m[mf][1], rm1);
            const float cor0 = exp2f(m[mf][0] - mn0);
            const float cor1 = exp2f(m[mf][1] - mn1);
            m[mf][0] = mn0; m[mf][1] = mn1;
            lacc[mf][0] *= cor0; lacc[mf][1] *= cor0;
            lacc[mf][2] *= cor1; lacc[mf][3] *= cor1;
#pragma unroll
            for (int nf = 0; nf < 8; nf++) {
                o[mf][nf][0] *= cor0; o[mf][nf][1] *= cor0;
                o[mf][nf][2] *= cor1; o[mf][nf][3] *= cor1;
                c[mf][nf][0] -= mn0;  c[mf][nf][1] -= mn0;
                c[mf][nf][2] -= mn1;  c[mf][nf][3] -= mn1;
            }
        }

        // ---- P = 2^c (fp16x2), l += P·1 (ones-MMA), O += P·V ----
        const uint32_t Vb = Sb + 8192;
#pragma unroll
        for (int ks = 0; ks < 4; ks++) {
            uint32_t ah[2][4];
#pragma unroll
            for (int mf = 0; mf < 2; mf++) {
                ah[mf][0] = h2exp2(pk16(c[mf][2*ks][0],     c[mf][2*ks][1]));
                ah[mf][1] = h2exp2(pk16(c[mf][2*ks][2],     c[mf][2*ks][3]));
                ah[mf][2] = h2exp2(pk16(c[mf][2*ks + 1][0], c[mf][2*ks + 1][1]));
                ah[mf][3] = h2exp2(pk16(c[mf][2*ks + 1][2], c[mf][2*ks + 1][3]));
                mma16816(lacc[mf], ah[mf], onesb);
            }
#pragma unroll
            for (int n2 = 0; n2 < 4; n2++) {
                const uint32_t va = Vb + (uint32_t)(ks * 2048) + vRow +
                                    ((vCb + (uint32_t)(n2 * 32)) ^ vSw);
                uint32_t vh0[2], vh1[2];
                ldmx4t(vh0[0], vh0[1], vh1[0], vh1[1], va);
                mma16816(o[0][2*n2],     ah[0], vh0);
                mma16816(o[1][2*n2],     ah[1], vh0);
                mma16816(o[0][2*n2 + 1], ah[0], vh1);
                mma16816(o[1][2*n2 + 1], ah[1], vh1);
            }
        }
    }

    // ---- finalize: l lives in lacc fragments ----
    const int b = bh >> 4, h = bh & 15;
#pragma unroll
    for (int mf = 0; mf < 2; mf++) {
        const float inv0 = 1.f / lacc[mf][0];
        const float inv1 = 1.f / lacc[mf][2];
        const size_t r0 = (size_t)(b * T_ + qr0 + mf * 16) * C_ + h * HD_ + tq * 2;
        const size_t r1 = r0 + (size_t)8 * C_;
#pragma unroll
        for (int nf = 0; nf < 8; nf++) {
            *(uint32_t*)&g_att16[r0 + nf * 8] = pk16(o[mf][nf][0] * inv0, o[mf][nf][1] * inv0);
            *(uint32_t*)&g_att16[r1 + nf * 8] = pk16(o[mf][nf][2] * inv1, o[mf][nf][3] * inv1);
        }
    }
}

// ---------------------------------------------------------------------------
extern "C" void kernel_launch(void* const* d_in, const int* in_sizes, int n_in,
                              void* d_out, int out_size)
{
    const float* x  = (const float*)d_in[0];
    const float* Wq = (const float*)d_in[1];
    const float* Wk = (const float*)d_in[2];
    const float* Wv = (const float*)d_in[3];
    const float* Wo = (const float*)d_in[4];
    float* out = (float*)d_out;

    cudaFuncSetAttribute(gemm_mma<0>, cudaFuncAttributeMaxDynamicSharedMemorySize, GEMM_SMEM);
    cudaFuncSetAttribute(gemm_mma<1>, cudaFuncAttributeMaxDynamicSharedMemorySize, GEMM_SMEM);
    cudaFuncSetAttribute(attn_mma,    cudaFuncAttributeMaxDynamicSharedMemorySize, ATT_SMEM);

    conv_kernel<<<2048, 256>>>(x, Wq, Wk, Wv, Wo);

    dim3 qkv_grid(C_ / 128, M_ / 128, 3);    // (8, 32, 3)
    gemm_mma<0><<<qkv_grid, 128, GEMM_SMEM>>>(nullptr);

    dim3 attn_grid(T_ / 128, B_ * H_);       // (16, 32)
    attn_mma<<<attn_grid, 128, ATT_SMEM>>>();

    dim3 out_grid(C_ / 128, M_ / 128, 1);    // (8, 32)
    gemm_mma<1><<<out_grid, 128, GEMM_SMEM>>>(out);
}

// round 17
// speedup vs baseline: 1.0021x; 1.0021x over previous
#include <cuda_runtime.h>
#include <cuda_fp16.h>
#include <math.h>
#include <stdint.h>

#define B_   2
#define T_   2048
#define C_   1024
#define H_   16
#define HD_  64
#define WIN_ 512
#define M_   (B_ * T_)

// ---------------------------------------------------------------------------
// Device scratch (allocation-free) — single fp16 everywhere
// ---------------------------------------------------------------------------
__device__ __half g_q16[(size_t)B_ * H_ * T_ * HD_];
__device__ __half g_k16[(size_t)B_ * H_ * T_ * HD_];
__device__ __half g_v16[(size_t)B_ * H_ * T_ * HD_];
__device__ __half g_x16[(size_t)M_ * C_];
__device__ __half g_w16[(size_t)4 * C_ * C_];   // Wq,Wk,Wv,Wo stacked
__device__ __half g_att16[(size_t)M_ * C_];

// ---------------------------------------------------------------------------
// PTX helpers
// ---------------------------------------------------------------------------
__device__ __forceinline__ uint32_t smem_u32(const void* p) {
    uint32_t a;
    asm("{ .reg .u64 t; cvta.to.shared.u64 t, %1; cvt.u32.u64 %0, t; }"
        : "=r"(a) : "l"(p));
    return a;
}

__device__ __forceinline__ void cp16(uint32_t s, const void* g) {
    asm volatile("cp.async.cg.shared.global [%0], [%1], 16;" :: "r"(s), "l"(g));
}
__device__ __forceinline__ void cp_commit() { asm volatile("cp.async.commit_group;"); }
__device__ __forceinline__ void cp_wait1()  { asm volatile("cp.async.wait_group 1;" ::: "memory"); }
__device__ __forceinline__ void cp_wait2()  { asm volatile("cp.async.wait_group 2;" ::: "memory"); }

__device__ __forceinline__ void ldmx4(uint32_t& r0, uint32_t& r1, uint32_t& r2, uint32_t& r3,
                                      uint32_t addr) {
    asm volatile("ldmatrix.sync.aligned.m8n8.x4.shared.b16 {%0,%1,%2,%3}, [%4];"
                 : "=r"(r0), "=r"(r1), "=r"(r2), "=r"(r3) : "r"(addr));
}
__device__ __forceinline__ void ldmx4t(uint32_t& r0, uint32_t& r1, uint32_t& r2, uint32_t& r3,
                                       uint32_t addr) {
    asm volatile("ldmatrix.sync.aligned.m8n8.x4.trans.shared.b16 {%0,%1,%2,%3}, [%4];"
                 : "=r"(r0), "=r"(r1), "=r"(r2), "=r"(r3) : "r"(addr));
}

// fp16 MMA, fp32 accumulate. Not volatile — ptxas may schedule.
__device__ __forceinline__ void mma16816(float* c, const uint32_t* a, const uint32_t* b) {
    asm("mma.sync.aligned.m16n8k16.row.col.f32.f16.f16.f32 "
        "{%0,%1,%2,%3}, {%4,%5,%6,%7}, {%8,%9}, {%0,%1,%2,%3};"
        : "+f"(c[0]), "+f"(c[1]), "+f"(c[2]), "+f"(c[3])
        : "r"(a[0]), "r"(a[1]), "r"(a[2]), "r"(a[3]), "r"(b[0]), "r"(b[1]));
}

// pack two fp32 into fp16x2 (a -> low half, b -> high half)
__device__ __forceinline__ uint32_t pk16(float a, float b) {
    uint32_t r;
    asm("cvt.rn.f16x2.f32 %0, %1, %2;" : "=r"(r) : "f"(b), "f"(a));
    return r;
}
// 2^x elementwise on fp16x2
__device__ __forceinline__ uint32_t h2exp2(uint32_t x) {
    uint32_t r;
    asm("ex2.approx.f16x2 %0, %1;" : "=r"(r) : "r"(x));
    return r;
}
// 2^x fp32 (force MUFU.EX2)
__device__ __forceinline__ float ex2f(float x) {
    float r;
    asm("ex2.approx.f32 %0, %1;" : "=f"(r) : "f"(x));
    return r;
}

// ---- Blackwell packed f32x2 scalar ops (PTX 8.6, sm_100+ family) ----
__device__ __forceinline__ uint64_t pkd(float a, float b) {
    uint64_t v;
    asm("mov.b64 %0, {%1, %2};" : "=l"(v) : "f"(a), "f"(b));
    return v;
}
__device__ __forceinline__ void mul2(float& x, float& y, uint64_t s) {
    uint64_t v = pkd(x, y);
    asm("mul.rn.f32x2 %0, %0, %1;" : "+l"(v) : "l"(s));
    asm("mov.b64 {%0, %1}, %2;" : "=f"(x), "=f"(y) : "l"(v));
}
__device__ __forceinline__ void add2(float& x, float& y, uint64_t s) {
    uint64_t v = pkd(x, y);
    asm("add.rn.f32x2 %0, %0, %1;" : "+l"(v) : "l"(s));
    asm("mov.b64 {%0, %1}, %2;" : "=f"(x), "=f"(y) : "l"(v));
}

// ---------------------------------------------------------------------------
// fp32 -> fp16 conversion (x and the 4 weight matrices).
// ---------------------------------------------------------------------------
__global__ __launch_bounds__(256)
void conv_kernel(const float* __restrict__ x,
                 const float* __restrict__ wq, const float* __restrict__ wk,
                 const float* __restrict__ wv, const float* __restrict__ wo)
{
    int i = blockIdx.x * 256 + threadIdx.x;
#pragma unroll
    for (int it = 0; it < 4; it++, i += 2048 * 256) {
        const float* src;
        __half* dst;
        size_t off;
        if (i < 1048576) {
            src = x + (size_t)i * 4;
            dst = g_x16; off = (size_t)i * 4;
        } else {
            const int r = i - 1048576;
            const int w = r >> 18;
            const float* ws = (w == 0) ? wq : (w == 1) ? wk : (w == 2) ? wv : wo;
            src = ws + (size_t)(r & 262143) * 4;
            dst = g_w16; off = (size_t)r * 4;
        }
        const float4 v = *(const float4*)src;
        *(uint32_t*)(dst + off)     = pk16(v.x, v.y);
        *(uint32_t*)(dst + off + 2) = pk16(v.z, v.w);
    }
}

// ---------------------------------------------------------------------------
// fp16 mma.sync GEMM (unchanged).
// CTA 128x128, BK=64, 128 threads: 4 warps as 2(M) x 2(N), warp tile 64x64.
// 2 CTAs/SM. 3-stage cp.async, one barrier/chunk.
// MODE 0: out -> fp16 q/k/v in [B,H,T,hd]; Q scaled by log2(e)/8.
// MODE 1: A = g_att16, W = Wo; out = fp32 [M,C].
// ---------------------------------------------------------------------------
#define STG_BYTES 32768              // A 16KB @0, B 16KB @16384
#define GEMM_SMEM (3 * STG_BYTES)    // 98304

template <int MODE>
__global__ void __launch_bounds__(128, 2)
gemm_mma(float* __restrict__ out)
{
    extern __shared__ char smem_raw[];
    const uint32_t smem = smem_u32(smem_raw);

    const int tid  = threadIdx.x;
    const int wid  = tid >> 5;
    const int lane = tid & 31;
    const int col0 = blockIdx.x * 128;
    const int row0 = blockIdx.y * 128;
    const int z    = blockIdx.z;

    const int wrow = wid & 1;        // M: 2 warps x 64
    const int wcol = wid >> 1;       // N: 2 warps x 64

    const __half* A16 = (MODE == 0) ? g_x16 : g_att16;
    const size_t woff = (MODE == 0 ? (size_t)z : 3) * ((size_t)C_ * C_);

    const __half* a16 = A16 + (size_t)row0 * C_;
    const __half* b16 = g_w16 + woff + (size_t)col0 * C_;

    auto load_stage = [&](int chunk, int s) {
        const int k0 = chunk * 64;
        const uint32_t st = smem + (uint32_t)s * STG_BYTES;
#pragma unroll
        for (int q = 0; q < 8; q++) {               // 1024 slots each for A,B
            const int slot = tid + q * 128;
            const int rr = slot >> 3;               // row 0..127
            const int ch = slot & 7;
            const uint32_t so = (uint32_t)(rr * 128 + ((ch ^ (rr & 7)) << 4));
            const size_t   go = (size_t)rr * C_ + k0 + ch * 8;
            cp16(st +         so, a16 + go);
            cp16(st + 16384 + so, b16 + go);
        }
        cp_commit();
    };

    float c[4][8][4];
#pragma unroll
    for (int mf = 0; mf < 4; mf++)
#pragma unroll
        for (int nf = 0; nf < 8; nf++)
#pragma unroll
            for (int e = 0; e < 4; e++) c[mf][nf][e] = 0.f;

    const int      rA    = lane & 15;
    const uint32_t aRow  = (uint32_t)(rA * 128);
    const uint32_t aSw   = (uint32_t)((rA & 7) << 4);
    const uint32_t aCb   = (uint32_t)((lane >> 4) << 4);          // 0 or 16
    const int      rB    = (lane & 7) + ((lane & 16) >> 1);
    const uint32_t bRow  = (uint32_t)(rB * 128);
    const uint32_t bSw   = (uint32_t)((rB & 7) << 4);
    const uint32_t bCb   = (uint32_t)((lane & 8) << 1);           // 0 or 16

    load_stage(0, 0);
    load_stage(1, 1);

    for (int ck = 0; ck < 16; ck++) {
        cp_wait1();
        __syncthreads();
        if (ck + 2 < 16) load_stage(ck + 2, (ck + 2) % 3);
        else             cp_commit();                  // keep group count uniform

        const uint32_t st = smem + (uint32_t)(ck % 3) * STG_BYTES;
        const uint32_t Abase = st + (uint32_t)(wrow * 8192) + aRow;           // 64 rows
        const uint32_t Bbase = st + 16384 + (uint32_t)(wcol * 8192) + bRow;   // 64 rows

#pragma unroll
        for (int k16 = 0; k16 < 4; k16++) {
            const uint32_t ca = ((aCb + (uint32_t)(k16 * 32)) ^ aSw);
            const uint32_t cb = ((bCb + (uint32_t)(k16 * 32)) ^ bSw);
            uint32_t af[4][4];
#pragma unroll
            for (int mf = 0; mf < 4; mf++) {
                const uint32_t a = Abase + (uint32_t)(mf * 2048) + ca;
                ldmx4(af[mf][0], af[mf][1], af[mf][2], af[mf][3], a);
            }
#pragma unroll
            for (int np = 0; np < 4; np++) {
                const uint32_t b = Bbase + (uint32_t)(np * 2048) + cb;
                uint32_t b0[2], b1[2];
                ldmx4(b0[0], b0[1], b1[0], b1[1], b);
                const int nf = np * 2;
#pragma unroll
                for (int mf = 0; mf < 4; mf++) mma16816(c[mf][nf],     af[mf], b0);
#pragma unroll
                for (int mf = 0; mf < 4; mf++) mma16816(c[mf][nf + 1], af[mf], b1);
            }
        }
    }

    // ---- epilogue ----
    const int group = lane >> 2;
    const int tq    = lane & 3;
#pragma unroll
    for (int mf = 0; mf < 4; mf++) {
#pragma unroll
        for (int nf = 0; nf < 8; nf++) {
            const int ncol = wcol * 64 + nf * 8 + tq * 2;
#pragma unroll
            for (int half = 0; half < 2; half++) {
                const int mrow = wrow * 64 + mf * 16 + group + half * 8;
                const int m = row0 + mrow;
                if (MODE == 0) {
                    __half* dst;
                    float sc;
                    // Q scale folds softmax 1/sqrt(64) AND log2(e).
                    if (z == 0)      { dst = g_q16; sc = 0.18033688011f; }
                    else if (z == 1) { dst = g_k16; sc = 1.0f;   }
                    else             { dst = g_v16; sc = 1.0f;   }
                    const uint32_t hv = pk16(c[mf][nf][half * 2]     * sc,
                                             c[mf][nf][half * 2 + 1] * sc);
                    const int n = col0 + ncol;
                    const int b = m >> 11;
                    const int t = m & (T_ - 1);
                    const int h = n >> 6;
                    const int d = n & 63;
                    const size_t idx = (((size_t)(b * H_ + h) * T_) + t) * HD_ + d;
                    *(uint32_t*)&dst[idx] = hv;
                } else {
                    const float2 v2 = make_float2(c[mf][nf][half * 2],
                                                  c[mf][nf][half * 2 + 1]);
                    *(float2*)&out[(size_t)m * C_ + col0 + ncol] = v2;
                }
            }
        }
    }
}

// ---------------------------------------------------------------------------
// fp16 tensor-core sliding-window flash attention — base-2 softmax with
// ones-MMA row sums; o-correction and score-subtract now use packed
// mul.rn.f32x2 / add.rn.f32x2 (halves the scalar-pipe issue count of the
// softmax, which the round-16 audit showed is issue-bound).
// CTA: 128 q x one (b,h); 128 threads: 4 warps x 32 q rows. 2 CTAs/SM.
// ---------------------------------------------------------------------------
#define ATT_STAGE  16384                          // K @0 (8KB), V @8192 (8KB)
#define ATT_SMEM   (3 * ATT_STAGE + 16384)        // 65536
#define MASKV      (-3.3e38f)

__global__ void __launch_bounds__(128, 2)
attn_mma()
{
    extern __shared__ char sraw[];
    const uint32_t ST = smem_u32(sraw);
    const uint32_t Qb = ST + 3 * ATT_STAGE;       // 16 KB Q region

    const int bh  = blockIdx.y;
    // long-first q-block permutation: {4..11, 3,12, 2,13, 1,14, 0,15}
    int qx;
    {
        const int bx = blockIdx.x;
        if (bx < 8) qx = 4 + bx;
        else {
            const int r = bx - 8;
            qx = (r & 1) ? (12 + (r >> 1)) : (3 - (r >> 1));
        }
    }
    const int q0  = qx * 128;
    const int tid = threadIdx.x;
    const int w    = tid >> 5;
    const int lane = tid & 31;

    // ---- Q staging ----
    {
        const __half* q16 = g_q16 + ((size_t)bh * T_ + q0) * HD_;
#pragma unroll
        for (int t = 0; t < 8; t++) {
            const int slot = tid + t * 128;        // 0..1023
            const int row = slot >> 3, ch = slot & 7;
            const uint32_t so = (uint32_t)(row * 128 + ((ch ^ (row & 7)) << 4));
            cp16(Qb + so, q16 + (size_t)row * HD_ + ch * 8);
        }
        cp_commit();
    }

    int kstart = q0 - (WIN_ - 1);
    if (kstart < 0) kstart = 0;
    kstart &= ~63;
    int kend = q0 + 128 + (WIN_ - 1);
    if (kend > T_) kend = T_;
    const int ntiles = (kend - kstart + 63) >> 6;

    auto load_stage = [&](int i) {
        const int kb = kstart + i * 64;
        if (kb < kend) {
            const uint32_t Sb = ST + (uint32_t)(i % 3) * ATT_STAGE;
            const size_t gb = ((size_t)bh * T_ + kb) * HD_;
#pragma unroll
            for (int t = 0; t < 4; t++) {
                const int slot = tid + t * 128;    // 0..511
                const int row = slot >> 3, ch = slot & 7;
                const uint32_t so = (uint32_t)(row * 128 + ((ch ^ (row & 7)) << 4));
                const size_t   go = gb + (size_t)row * HD_ + ch * 8;
                cp16(Sb +        so, g_k16 + go);
                cp16(Sb + 8192 + so, g_v16 + go);
            }
        }
        cp_commit();
    };

    load_stage(0);
    load_stage(1);
    cp_wait2();              // Q ready (stages 0,1 may still be in flight)
    __syncthreads();

    // ---- Q fragments to registers: 2 mf x 4 ks ----
    uint32_t qf[2][4][4];
    {
        const uint32_t qSw  = (uint32_t)((lane & 7) << 4);
        const uint32_t qCb  = (uint32_t)((lane >> 4) << 4);
#pragma unroll
        for (int mf = 0; mf < 2; mf++) {
            const uint32_t qRow = (uint32_t)((w * 32 + mf * 16 + (lane & 15)) * 128);
#pragma unroll
            for (int ks = 0; ks < 4; ks++) {
                const uint32_t a = Qb + qRow + ((qCb + (uint32_t)(ks * 32)) ^ qSw);
                ldmx4(qf[mf][ks][0], qf[mf][ks][1], qf[mf][ks][2], qf[mf][ks][3], a);
            }
        }
    }

    float m[2][2];
#pragma unroll
    for (int mf = 0; mf < 2; mf++) { m[mf][0] = MASKV; m[mf][1] = MASKV; }
    float lacc[2][4];                 // row-sum accumulator fragments (ones-MMA)
#pragma unroll
    for (int mf = 0; mf < 2; mf++)
#pragma unroll
        for (int e = 0; e < 4; e++) lacc[mf][e] = 0.f;
    float o[2][8][4];
#pragma unroll
    for (int mf = 0; mf < 2; mf++)
#pragma unroll
        for (int nf = 0; nf < 8; nf++)
#pragma unroll
            for (int e = 0; e < 4; e++) o[mf][nf][e] = 0.f;

    const uint32_t onesb[2] = {0x3C003C00u, 0x3C003C00u};   // fp16 1.0 x4

    const int g  = lane >> 2;
    const int tq = lane & 3;
    const int qr0 = q0 + w * 32 + g;

    const int      rK   = (lane & 7) + ((lane & 16) >> 1);
    const uint32_t kRow = (uint32_t)(rK * 128);
    const uint32_t kSw  = (uint32_t)((rK & 7) << 4);
    const uint32_t kCb  = (uint32_t)((lane & 8) << 1);            // 0 or 16
    const int      rV   = lane & 15;
    const uint32_t vRow = (uint32_t)(rV * 128);
    const uint32_t vSw  = (uint32_t)((rV & 7) << 4);
    const uint32_t vCb  = (uint32_t)(lane & 16);                  // 0 or 16

    for (int i = 0; i < ntiles; i++) {
        cp_wait1();
        __syncthreads();
        load_stage(i + 2);   // overwrites stage consumed at i-1

        const uint32_t Sb = ST + (uint32_t)(i % 3) * ATT_STAGE;
        const int kb = kstart + i * 64;

        // ---- S = Q K^T (log2-domain scores) ----
        float c[2][8][4];
#pragma unroll
        for (int mf = 0; mf < 2; mf++)
#pragma unroll
            for (int nf = 0; nf < 8; nf++)
#pragma unroll
                for (int e = 0; e < 4; e++) c[mf][nf][e] = 0.f;

#pragma unroll
        for (int ks = 0; ks < 4; ks++) {
            const uint32_t cc = (kCb + (uint32_t)(ks * 32)) ^ kSw;
#pragma unroll
            for (int np = 0; np < 4; np++) {
                const uint32_t addr = Sb + (uint32_t)(np * 2048) + kRow + cc;
                uint32_t b0[2], b1[2];
                ldmx4(b0[0], b0[1], b1[0], b1[1], addr);
                mma16816(c[0][2*np],     qf[0][ks], b0);
                mma16816(c[1][2*np],     qf[1][ks], b0);
                mma16816(c[0][2*np + 1], qf[0][ks], b1);
                mma16816(c[1][2*np + 1], qf[1][ks], b1);
            }
        }

        // ---- mask (edge tiles only) ----
        if (kb < q0 - 384 || kb > q0 + 448) {
#pragma unroll
            for (int mf = 0; mf < 2; mf++)
#pragma unroll
                for (int nf = 0; nf < 8; nf++)
#pragma unroll
                    for (int e = 0; e < 4; e++) {
                        const int key = kb + nf * 8 + tq * 2 + (e & 1);
                        const int qq  = qr0 + mf * 16 + ((e >> 1) << 3);
                        const int d   = qq - key;
                        if (d > (WIN_ - 1) || d < -(WIN_ - 1)) c[mf][nf][e] = MASKV;
                    }
        }

        // ---- online softmax (base 2), packed f32x2 correction/subtract ----
#pragma unroll
        for (int mf = 0; mf < 2; mf++) {
            float rm0 = MASKV, rm1 = MASKV;
#pragma unroll
            for (int nf = 0; nf < 8; nf++) {
                rm0 = fmaxf(rm0, fmaxf(c[mf][nf][0], c[mf][nf][1]));
                rm1 = fmaxf(rm1, fmaxf(c[mf][nf][2], c[mf][nf][3]));
            }
            rm0 = fmaxf(rm0, __shfl_xor_sync(0xffffffff, rm0, 1));
            rm0 = fmaxf(rm0, __shfl_xor_sync(0xffffffff, rm0, 2));
            rm1 = fmaxf(rm1, __shfl_xor_sync(0xffffffff, rm1, 1));
            rm1 = fmaxf(rm1, __shfl_xor_sync(0xffffffff, rm1, 2));

            const float mn0 = fmaxf(m[mf][0], rm0);
            const float mn1 = fmaxf(m[mf][1], rm1);
            const float cor0 = ex2f(m[mf][0] - mn0);
            const float cor1 = ex2f(m[mf][1] - mn1);
            m[mf][0] = mn0; m[mf][1] = mn1;

            const uint64_t c0p = pkd(cor0, cor0);
            const uint64_t c1p = pkd(cor1, cor1);
            const uint64_t s0p = pkd(-mn0, -mn0);
            const uint64_t s1p = pkd(-mn1, -mn1);

            mul2(lacc[mf][0], lacc[mf][1], c0p);
            mul2(lacc[mf][2], lacc[mf][3], c1p);
#pragma unroll
            for (int nf = 0; nf < 8; nf++) {
                mul2(o[mf][nf][0], o[mf][nf][1], c0p);
                mul2(o[mf][nf][2], o[mf][nf][3], c1p);
                add2(c[mf][nf][0], c[mf][nf][1], s0p);
                add2(c[mf][nf][2], c[mf][nf][3], s1p);
            }
        }

        // ---- P = 2^c (fp16x2), l += P·1 (ones-MMA), O += P·V ----
        const uint32_t Vb = Sb + 8192;
#pragma unroll
        for (int ks = 0; ks < 4; ks++) {
            uint32_t ah[2][4];
#pragma unroll
            for (int mf = 0; mf < 2; mf++) {
                ah[mf][0] = h2exp2(pk16(c[mf][2*ks][0],     c[mf][2*ks][1]));
                ah[mf][1] = h2exp2(pk16(c[mf][2*ks][2],     c[mf][2*ks][3]));
                ah[mf][2] = h2exp2(pk16(c[mf][2*ks + 1][0], c[mf][2*ks + 1][1]));
                ah[mf][3] = h2exp2(pk16(c[mf][2*ks + 1][2], c[mf][2*ks + 1][3]));
                mma16816(lacc[mf], ah[mf], onesb);
            }
#pragma unroll
            for (int n2 = 0; n2 < 4; n2++) {
                const uint32_t va = Vb + (uint32_t)(ks * 2048) + vRow +
                                    ((vCb + (uint32_t)(n2 * 32)) ^ vSw);
                uint32_t vh0[2], vh1[2];
                ldmx4t(vh0[0], vh0[1], vh1[0], vh1[1], va);
                mma16816(o[0][2*n2],     ah[0], vh0);
                mma16816(o[1][2*n2],     ah[1], vh0);
                mma16816(o[0][2*n2 + 1], ah[0], vh1);
                mma16816(o[1][2*n2 + 1], ah[1], vh1);
            }
        }
    }

    // ---- finalize: l lives in lacc fragments ----
    const int b = bh >> 4, h = bh & 15;
#pragma unroll
    for (int mf = 0; mf < 2; mf++) {
        const float inv0 = 1.f / lacc[mf][0];
        const float inv1 = 1.f / lacc[mf][2];
        const size_t r0 = (size_t)(b * T_ + qr0 + mf * 16) * C_ + h * HD_ + tq * 2;
        const size_t r1 = r0 + (size_t)8 * C_;
#pragma unroll
        for (int nf = 0; nf < 8; nf++) {
            *(uint32_t*)&g_att16[r0 + nf * 8] = pk16(o[mf][nf][0] * inv0, o[mf][nf][1] * inv0);
            *(uint32_t*)&g_att16[r1 + nf * 8] = pk16(o[mf][nf][2] * inv1, o[mf][nf][3] * inv1);
        }
    }
}

// ---------------------------------------------------------------------------
extern "C" void kernel_launch(void* const* d_in, const int* in_sizes, int n_in,
                              void* d_out, int out_size)
{
    const float* x  = (const float*)d_in[0];
    const float* Wq = (const float*)d_in[1];
    const float* Wk = (const float*)d_in[2];
    const float* Wv = (const float*)d_in[3];
    const float* Wo = (const float*)d_in[4];
    float* out = (float*)d_out;

    cudaFuncSetAttribute(gemm_mma<0>, cudaFuncAttributeMaxDynamicSharedMemorySize, GEMM_SMEM);
    cudaFuncSetAttribute(gemm_mma<1>, cudaFuncAttributeMaxDynamicSharedMemorySize, GEMM_SMEM);
    cudaFuncSetAttribute(attn_mma,    cudaFuncAttributeMaxDynamicSharedMemorySize, ATT_SMEM);

    conv_kernel<<<2048, 256>>>(x, Wq, Wk, Wv, Wo);

    dim3 qkv_grid(C_ / 128, M_ / 128, 3);    // (8, 32, 3)
    gemm_mma<0><<<qkv_grid, 128, GEMM_SMEM>>>(nullptr);

    dim3 attn_grid(T_ / 128, B_ * H_);       // (16, 32)
    attn_mma<<<attn_grid, 128, ATT_SMEM>>>();

    dim3 out_grid(C_ / 128, M_ / 128, 1);    // (8, 32)
    gemm_mma<1><<<out_grid, 128, GEMM_SMEM>>>(out);
}